// round 3
// baseline (speedup 1.0000x reference)
#include <cuda_runtime.h>
#include <cstdint>
#include <cstddef>

#define NTOK 4096
#define NCH  512
#define NBATCH 2

// Scratch: T,Q,K,V,O (2*4096*512 each = 5*4194304) + scores (2*4096*4096 = 33554432)
// total = 54525952 floats (~218 MB), static bss — allowed (no runtime allocation).
__device__ float g_scratch[54525952];

// ---------------------------------------------------------------------------
// Packed f32x2 helpers (sm_100+ FFMA2: 2x fp32 FMA throughput vs scalar FFMA)
// ---------------------------------------------------------------------------
__device__ __forceinline__ unsigned long long dup2(float a) {
    unsigned long long d;
    unsigned int u = __float_as_uint(a);
    asm("mov.b64 %0, {%1, %1};" : "=l"(d) : "r"(u));
    return d;
}
__device__ __forceinline__ void ffma2(unsigned long long& d,
                                      unsigned long long a,
                                      unsigned long long b) {
    asm("fma.rn.f32x2 %0, %1, %2, %0;" : "+l"(d) : "l"(a), "l"(b));
}

// ---------------------------------------------------------------------------
// GroupNorm: one block per (batch, group). Reads x[b][16g..16g+15][0..4095]
// (one contiguous 64K-float chunk), writes transposed tT[b][p][c] so the
// downstream GEMMs see row-major [n, c]. smem tile transpose keeps both the
// global reads and writes coalesced.
// ---------------------------------------------------------------------------
__global__ __launch_bounds__(256) void gn_kernel(const float* __restrict__ x,
                                                 const float* __restrict__ sc,
                                                 const float* __restrict__ bi,
                                                 float* __restrict__ t) {
    int b = blockIdx.x >> 5;
    int g = blockIdx.x & 31;
    const float* base = x + ((size_t)(b * NCH + g * 16)) * NTOK;
    int tid = threadIdx.x;

    // Pass 1: sum / sumsq over 65536 elements
    float s = 0.f, ss = 0.f;
    const float4* b4 = (const float4*)base;
    for (int i = tid; i < 16 * NTOK / 4; i += 256) {
        float4 v = b4[i];
        s  += v.x + v.y + v.z + v.w;
        ss += v.x * v.x + v.y * v.y + v.z * v.z + v.w * v.w;
    }
    __shared__ float rs[256], rss[256];
    rs[tid] = s; rss[tid] = ss;
    __syncthreads();
    for (int st = 128; st > 0; st >>= 1) {
        if (tid < st) { rs[tid] += rs[tid + st]; rss[tid] += rss[tid + st]; }
        __syncthreads();
    }
    float mean = rs[0] * (1.f / 65536.f);
    float var  = rss[0] * (1.f / 65536.f) - mean * mean;
    float inv  = rsqrtf(var + 1e-6f);

    __shared__ float Acf[16], Bcf[16];
    if (tid < 16) {
        float scv = sc[g * 16 + tid], biv = bi[g * 16 + tid];
        Acf[tid] = scv * inv;
        Bcf[tid] = biv - mean * scv * inv;
    }
    __shared__ float tile[16][257];   // +1 pad: conflict-free transposed reads
    __syncthreads();

    // Pass 2: normalize + transpose via smem, 16 tiles of 16ch x 256p
    for (int tb = 0; tb < 16; tb++) {
        int p0 = tb * 256;
        for (int idx = tid; idx < 4096; idx += 256) {
            int cc = idx >> 8, pp = idx & 255;
            tile[cc][pp] = base[cc * NTOK + p0 + pp] * Acf[cc] + Bcf[cc];
        }
        __syncthreads();
        for (int idx = tid; idx < 4096; idx += 256) {
            int pp = idx >> 4, cc = idx & 15;
            t[((size_t)(b * NTOK + p0 + pp)) * NCH + g * 16 + cc] = tile[cc][pp];
        }
        __syncthreads();
    }
}

// ---------------------------------------------------------------------------
// Universal GEMM: C[M,N] = alpha * A[M,K] * B[N,K]^T  (+ row bias, col bias,
// residual). 128x128x8 tiles, 256 threads, 8x8 micro-tile per thread held as
// 32 packed f32x2 accumulators driven by fma.rn.f32x2 (FFMA2).
// All problem dims here are multiples of 128 / BK=8, so no bounds checks.
// ---------------------------------------------------------------------------
__global__ __launch_bounds__(256) void gemm_abt(
    const float* __restrict__ A, const float* __restrict__ B,
    float* __restrict__ C,
    int M, int N, int K,
    size_t sA, size_t sB, size_t sC,
    float alpha,
    const float* __restrict__ bias_row,   // len M (indexed by output row)
    const float* __restrict__ bias_col,   // len N (indexed by output col)
    const float* __restrict__ res, size_t sRes) {
    A += (size_t)blockIdx.z * sA;
    B += (size_t)blockIdx.z * sB;
    C += (size_t)blockIdx.z * sC;
    if (res) res += (size_t)blockIdx.z * sRes;

    __shared__ float As[8][128];
    __shared__ float Bs[8][128];
    int tid = threadIdx.x;
    int bm = blockIdx.y * 128, bn = blockIdx.x * 128;
    int lr = tid >> 1;            // 0..127 tile row loaded by this thread
    int lc = (tid & 1) << 2;      // 0 or 4 within K-slab
    int ty = tid >> 4, tx = tid & 15;
    const float* Ap = A + (size_t)(bm + lr) * K + lc;
    const float* Bp = B + (size_t)(bn + lr) * K + lc;

    unsigned long long acc[8][4];
#pragma unroll
    for (int i = 0; i < 8; i++)
#pragma unroll
        for (int j = 0; j < 4; j++) acc[i][j] = 0ull;

    for (int k0 = 0; k0 < K; k0 += 8) {
        float4 av = *(const float4*)(Ap + k0);
        float4 bv = *(const float4*)(Bp + k0);
        As[lc + 0][lr] = av.x; As[lc + 1][lr] = av.y;
        As[lc + 2][lr] = av.z; As[lc + 3][lr] = av.w;
        Bs[lc + 0][lr] = bv.x; Bs[lc + 1][lr] = bv.y;
        Bs[lc + 2][lr] = bv.z; Bs[lc + 3][lr] = bv.w;
        __syncthreads();
#pragma unroll
        for (int kk = 0; kk < 8; kk++) {
            float4 a0 = *(const float4*)&As[kk][ty * 8];
            float4 a1 = *(const float4*)&As[kk][ty * 8 + 4];
            ulonglong2 b0 = *(const ulonglong2*)&Bs[kk][tx * 8];
            ulonglong2 b1 = *(const ulonglong2*)&Bs[kk][tx * 8 + 4];
            unsigned long long ad[8];
            ad[0] = dup2(a0.x); ad[1] = dup2(a0.y);
            ad[2] = dup2(a0.z); ad[3] = dup2(a0.w);
            ad[4] = dup2(a1.x); ad[5] = dup2(a1.y);
            ad[6] = dup2(a1.z); ad[7] = dup2(a1.w);
            unsigned long long bd[4] = { b0.x, b0.y, b1.x, b1.y };
#pragma unroll
            for (int i = 0; i < 8; i++)
#pragma unroll
                for (int j = 0; j < 4; j++)
                    ffma2(acc[i][j], ad[i], bd[j]);
        }
        __syncthreads();
    }

#pragma unroll
    for (int i = 0; i < 8; i++) {
        int r = bm + ty * 8 + i;
        float brow = bias_row ? bias_row[r] : 0.f;
        size_t rowoff = (size_t)r * N;
#pragma unroll
        for (int j = 0; j < 4; j++) {
            unsigned int lo, hi;
            asm("mov.b64 {%0, %1}, %2;" : "=r"(lo), "=r"(hi) : "l"(acc[i][j]));
            int c0 = bn + tx * 8 + j * 2;
            float v0 = __uint_as_float(lo) * alpha + brow;
            float v1 = __uint_as_float(hi) * alpha + brow;
            if (bias_col) { v0 += bias_col[c0]; v1 += bias_col[c0 + 1]; }
            if (res)      { v0 += res[rowoff + c0]; v1 += res[rowoff + c0 + 1]; }
            C[rowoff + c0]     = v0;
            C[rowoff + c0 + 1] = v1;
        }
    }
}

// ---------------------------------------------------------------------------
// Row softmax, in place: one block per row of 4096 fp32 values. Row lives in
// registers (16 values/thread); two smem tree reductions (max, sum).
// ---------------------------------------------------------------------------
__global__ __launch_bounds__(256) void softmax_kernel(float* __restrict__ S) {
    float4* p = (float4*)(S + (size_t)blockIdx.x * NTOK);
    int tid = threadIdx.x;
    float4 loc[4];
    float m = -3.4e38f;
#pragma unroll
    for (int i = 0; i < 4; i++) {
        float4 v = p[tid + i * 256];
        loc[i] = v;
        m = fmaxf(m, fmaxf(fmaxf(v.x, v.y), fmaxf(v.z, v.w)));
    }
    __shared__ float red[256];
    red[tid] = m; __syncthreads();
    for (int st = 128; st > 0; st >>= 1) {
        if (tid < st) red[tid] = fmaxf(red[tid], red[tid + st]);
        __syncthreads();
    }
    m = red[0];
    __syncthreads();
    float ssum = 0.f;
#pragma unroll
    for (int i = 0; i < 4; i++) {
        loc[i].x = __expf(loc[i].x - m);
        loc[i].y = __expf(loc[i].y - m);
        loc[i].z = __expf(loc[i].z - m);
        loc[i].w = __expf(loc[i].w - m);
        ssum += loc[i].x + loc[i].y + loc[i].z + loc[i].w;
    }
    red[tid] = ssum; __syncthreads();
    for (int st = 128; st > 0; st >>= 1) {
        if (tid < st) red[tid] += red[tid + st];
        __syncthreads();
    }
    float inv = 1.f / red[0];
#pragma unroll
    for (int i = 0; i < 4; i++) {
        float4 v = loc[i];
        v.x *= inv; v.y *= inv; v.z *= inv; v.w *= inv;
        p[tid + i * 256] = v;
    }
}

// ---------------------------------------------------------------------------
// Launch graph:
//   GN -> tT[b,n,c]
//   Q[b,n,c]  = tT . wq^T + bq          (col bias)
//   K[b,n,c]  = tT . wk^T + bk          (col bias)
//   V[b,c,n]  = wv . tT^T + bv          (row bias)
//   S[b,n,n]  = (Q . K^T) * c^-0.5
//   softmax rows of S
//   O[b,n,c]  = S . V^T
//   Y[b,c,n]  = wp . O^T + bp + x       (row bias + residual)
// ---------------------------------------------------------------------------
extern "C" void kernel_launch(void* const* d_in, const int* in_sizes, int n_in,
                              void* d_out, int out_size) {
    const float* x  = (const float*)d_in[0];
    const float* gs = (const float*)d_in[1];
    const float* gb = (const float*)d_in[2];
    const float* wq = (const float*)d_in[3];
    const float* bq = (const float*)d_in[4];
    const float* wk = (const float*)d_in[5];
    const float* bk = (const float*)d_in[6];
    const float* wv = (const float*)d_in[7];
    const float* bv = (const float*)d_in[8];
    const float* wp = (const float*)d_in[9];
    const float* bp = (const float*)d_in[10];
    float* y = (float*)d_out;

    float* scratch = nullptr;
    cudaGetSymbolAddress((void**)&scratch, g_scratch);
    const size_t NB1 = (size_t)NTOK * NCH;       // 2097152 per batch
    float* T  = scratch;                // tT [b][n][c]
    float* Q  = scratch + 2 * NB1;      // [b][n][c]
    float* Km = scratch + 4 * NB1;      // [b][n][c]
    float* V  = scratch + 6 * NB1;      // [b][c][n]
    float* O  = scratch + 8 * NB1;      // [b][n][c]
    float* Sc = scratch + 10 * NB1;     // [b][n][n]
    const size_t sS = (size_t)NTOK * NTOK;

    gn_kernel<<<64, 256>>>(x, gs, gb, T);

    gemm_abt<<<dim3(4, 32, 2), 256>>>(T, wq, Q, NTOK, NCH, NCH,
                                      NB1, 0, NB1, 1.f, nullptr, bq, nullptr, 0);
    gemm_abt<<<dim3(4, 32, 2), 256>>>(T, wk, Km, NTOK, NCH, NCH,
                                      NB1, 0, NB1, 1.f, nullptr, bk, nullptr, 0);
    gemm_abt<<<dim3(32, 4, 2), 256>>>(wv, T, V, NCH, NTOK, NCH,
                                      0, NB1, NB1, 1.f, bv, nullptr, nullptr, 0);

    gemm_abt<<<dim3(32, 32, 2), 256>>>(Q, Km, Sc, NTOK, NTOK, NCH,
                                       NB1, NB1, sS,
                                       0.044194173824159216f,  // 512^-0.5
                                       nullptr, nullptr, nullptr, 0);

    softmax_kernel<<<NBATCH * NTOK, 256>>>(Sc);

    gemm_abt<<<dim3(4, 32, 2), 256>>>(Sc, V, O, NTOK, NCH, NTOK,
                                      sS, NB1, NB1, 1.f, nullptr, nullptr, nullptr, 0);

    gemm_abt<<<dim3(32, 4, 2), 256>>>(wp, O, y, NCH, NTOK, NCH,
                                      0, NB1, NB1, 1.f, bp, nullptr, x, NB1);
}

// round 5
// speedup vs baseline: 5.2078x; 5.2078x over previous
#include <cuda_runtime.h>
#include <cuda_bf16.h>
#include <cstdint>
#include <cstddef>

#define NTOK 4096
#define NCH  512

typedef __nv_bfloat16 bf16;

// 256 MB static scratch (bss) — no runtime allocation.
__device__ float g_scratch[64u * 1024u * 1024u];

// ---------------------------------------------------------------------------
// PTX helpers (base sm_100 ISA only: cp.async, ldmatrix, mma.sync)
// ---------------------------------------------------------------------------
__device__ __forceinline__ uint32_t s2u(const void* p) {
    uint32_t r;
    asm("{ .reg .u64 t; cvta.to.shared.u64 t, %1; cvt.u32.u64 %0, t; }"
        : "=r"(r) : "l"(p));
    return r;
}
#define CP_ASYNC16(s, g)                                                       \
    asm volatile("cp.async.cg.shared.global [%0], [%1], 16;" ::                \
                 "r"(s), "l"(g))
#define CP_COMMIT() asm volatile("cp.async.commit_group;" ::: "memory")
#define CP_WAIT(n)  asm volatile("cp.async.wait_group %0;" :: "n"(n) : "memory")

__device__ __forceinline__ void ldm_x4(uint32_t& r0, uint32_t& r1,
                                       uint32_t& r2, uint32_t& r3,
                                       uint32_t addr) {
    asm volatile("ldmatrix.sync.aligned.m8n8.x4.shared.b16 {%0,%1,%2,%3}, [%4];"
                 : "=r"(r0), "=r"(r1), "=r"(r2), "=r"(r3) : "r"(addr));
}
__device__ __forceinline__ void mma16816(float* c, const uint32_t* a,
                                         uint32_t b0, uint32_t b1) {
    asm volatile(
        "mma.sync.aligned.m16n8k16.row.col.f32.bf16.bf16.f32 "
        "{%0,%1,%2,%3}, {%4,%5,%6,%7}, {%8,%9}, {%0,%1,%2,%3};"
        : "+f"(c[0]), "+f"(c[1]), "+f"(c[2]), "+f"(c[3])
        : "r"(a[0]), "r"(a[1]), "r"(a[2]), "r"(a[3]), "r"(b0), "r"(b1));
}

// ---------------------------------------------------------------------------
// GroupNorm: one block per (batch, group); writes transposed bf16 T[b][n][c].
// ---------------------------------------------------------------------------
__global__ __launch_bounds__(256) void gn_kernel(const float* __restrict__ x,
                                                 const float* __restrict__ sc,
                                                 const float* __restrict__ bi,
                                                 bf16* __restrict__ t) {
    int b = blockIdx.x >> 5;
    int g = blockIdx.x & 31;
    const float* base = x + ((size_t)(b * NCH + g * 16)) * NTOK;
    int tid = threadIdx.x;

    float s = 0.f, ss = 0.f;
    const float4* b4 = (const float4*)base;
    for (int i = tid; i < 16 * NTOK / 4; i += 256) {
        float4 v = b4[i];
        s  += v.x + v.y + v.z + v.w;
        ss += v.x * v.x + v.y * v.y + v.z * v.z + v.w * v.w;
    }
    __shared__ float rs[256], rss[256];
    rs[tid] = s; rss[tid] = ss;
    __syncthreads();
    for (int st = 128; st > 0; st >>= 1) {
        if (tid < st) { rs[tid] += rs[tid + st]; rss[tid] += rss[tid + st]; }
        __syncthreads();
    }
    float mean = rs[0] * (1.f / 65536.f);
    float var  = rss[0] * (1.f / 65536.f) - mean * mean;
    float inv  = rsqrtf(var + 1e-6f);

    __shared__ float Acf[16], Bcf[16];
    if (tid < 16) {
        float scv = sc[g * 16 + tid], biv = bi[g * 16 + tid];
        Acf[tid] = scv * inv;
        Bcf[tid] = biv - mean * scv * inv;
    }
    __shared__ float tile[16][257];
    __syncthreads();

    for (int tb = 0; tb < 16; tb++) {
        int p0 = tb * 256;
        for (int idx = tid; idx < 4096; idx += 256) {
            int cc = idx >> 8, pp = idx & 255;
            tile[cc][pp] = base[cc * NTOK + p0 + pp] * Acf[cc] + Bcf[cc];
        }
        __syncthreads();
        for (int idx = tid; idx < 4096; idx += 256) {
            int pp = idx >> 4, cc = idx & 15;
            t[((size_t)(b * NTOK + p0 + pp)) * NCH + g * 16 + cc] =
                __float2bfloat16(tile[cc][pp]);
        }
        __syncthreads();
    }
}

// ---------------------------------------------------------------------------
// fp32 -> bf16 weight conversion (262144 elements)
// ---------------------------------------------------------------------------
__global__ __launch_bounds__(256) void cvt_kernel(const float* __restrict__ in,
                                                  bf16* __restrict__ out) {
    int i = blockIdx.x * 256 + threadIdx.x;
    float4 v = ((const float4*)in)[i];
    __nv_bfloat162 a = __floats2bfloat162_rn(v.x, v.y);
    __nv_bfloat162 b = __floats2bfloat162_rn(v.z, v.w);
    ((__nv_bfloat162*)out)[2 * i]     = a;
    ((__nv_bfloat162*)out)[2 * i + 1] = b;
}

// ---------------------------------------------------------------------------
// bf16 mma.sync GEMM: C[M,N] = alpha * A[M,K] . B[N,K]^T (+biases/residual).
// CTA tile 128x128, BK=32, 8 warps (2 M x 4 N), warp tile 64x32.
// cp.async double-buffered smem (rows padded to 80B: conflict-free ldmatrix).
// grid = (N/128, M/128, batch). All dims are multiples of tile sizes.
// ---------------------------------------------------------------------------
#define STG_BYTES 20480   // A: 128*80, B: 128*80
__global__ __launch_bounds__(256, 2) void gemm_mma(
    const bf16* __restrict__ A, const bf16* __restrict__ B,
    int K, int ldC,
    size_t sA, size_t sB, size_t sC,
    float alpha,
    const float* __restrict__ brow, const float* __restrict__ bcol,
    const float* __restrict__ res, size_t sRes,
    float* __restrict__ Cf, bf16* __restrict__ Cb) {
    __shared__ __align__(16) char smem[2][STG_BYTES];

    const int tid = threadIdx.x;
    const int wid = tid >> 5, lane = tid & 31;
    const int wm = wid & 1, wn = wid >> 1;       // 2 x 4 warp grid
    const int bm = blockIdx.y * 128, bn = blockIdx.x * 128;
    A += (size_t)blockIdx.z * sA;
    B += (size_t)blockIdx.z * sB;
    const size_t coff = (size_t)blockIdx.z * sC;
    if (res) res += (size_t)blockIdx.z * sRes;

    const bf16* Ab = A + (size_t)bm * K;
    const bf16* Bb = B + (size_t)bn * K;
    const int NC = K >> 5;

    // loader: 512 16B chunks per operand tile, 2 per thread
    const int lr0 = tid >> 2;            // row for chunk j=0 (0..63)... u>>2
    const int lcb = (tid & 3) * 16;      // byte col within 64B row

    float acc[4][4][4];
#pragma unroll
    for (int mi = 0; mi < 4; mi++)
#pragma unroll
        for (int ni = 0; ni < 4; ni++)
#pragma unroll
            for (int q = 0; q < 4; q++) acc[mi][ni][q] = 0.f;

    // ldmatrix base offsets (bytes): row stride 80
    uint32_t aoff[4], boff[2];
#pragma unroll
    for (int mi = 0; mi < 4; mi++)
        aoff[mi] = (uint32_t)((wm * 64 + mi * 16 + (lane & 15)) * 80 +
                              (lane >> 4) * 16);
#pragma unroll
    for (int nb = 0; nb < 2; nb++)
        boff[nb] = (uint32_t)(10240 + (wn * 32 + nb * 16 + (lane & 15)) * 80 +
                              (lane >> 4) * 16);

    // ---- prologue: stage 0 ----
    {
        uint32_t sa = s2u(smem[0]);
#pragma unroll
        for (int j = 0; j < 2; j++) {
            int r = lr0 + j * 64;
            CP_ASYNC16(sa + r * 80 + lcb,
                       (const char*)(Ab + (size_t)r * K) + lcb);
            CP_ASYNC16(sa + 10240 + r * 80 + lcb,
                       (const char*)(Bb + (size_t)r * K) + lcb);
        }
        CP_COMMIT();
    }

    for (int i = 0; i < NC; i++) {
        if (i + 1 < NC) {
            uint32_t sa = s2u(smem[(i + 1) & 1]);
            const bf16* Ag = Ab + (i + 1) * 32;
            const bf16* Bg = Bb + (i + 1) * 32;
#pragma unroll
            for (int j = 0; j < 2; j++) {
                int r = lr0 + j * 64;
                CP_ASYNC16(sa + r * 80 + lcb,
                           (const char*)(Ag + (size_t)r * K) + lcb);
                CP_ASYNC16(sa + 10240 + r * 80 + lcb,
                           (const char*)(Bg + (size_t)r * K) + lcb);
            }
            CP_COMMIT();
            CP_WAIT(1);
        } else {
            CP_WAIT(0);
        }
        __syncthreads();

        uint32_t base = s2u(smem[i & 1]);
#pragma unroll
        for (int ks = 0; ks < 2; ks++) {
            uint32_t areg[4][4], breg[2][4];
#pragma unroll
            for (int mi = 0; mi < 4; mi++)
                ldm_x4(areg[mi][0], areg[mi][1], areg[mi][2], areg[mi][3],
                       base + aoff[mi] + ks * 32);
#pragma unroll
            for (int nb = 0; nb < 2; nb++)
                ldm_x4(breg[nb][0], breg[nb][1], breg[nb][2], breg[nb][3],
                       base + boff[nb] + ks * 32);
#pragma unroll
            for (int mi = 0; mi < 4; mi++)
#pragma unroll
                for (int ni = 0; ni < 4; ni++) {
                    uint32_t b0 = breg[ni >> 1][ni & 1];
                    uint32_t b1 = breg[ni >> 1][(ni & 1) + 2];
                    mma16816(acc[mi][ni], areg[mi], b0, b1);
                }
        }
        __syncthreads();
    }

    // ---- epilogue ----
    float bc[8];
#pragma unroll
    for (int ni = 0; ni < 4; ni++) {
        int col = bn + wn * 32 + ni * 8 + (lane & 3) * 2;
        bc[2 * ni]     = bcol ? bcol[col]     : 0.f;
        bc[2 * ni + 1] = bcol ? bcol[col + 1] : 0.f;
    }
#pragma unroll
    for (int mi = 0; mi < 4; mi++) {
#pragma unroll
        for (int h = 0; h < 2; h++) {
            int row = bm + wm * 64 + mi * 16 + (lane >> 2) + 8 * h;
            float rb = brow ? brow[row] : 0.f;
            size_t rowbase = coff + (size_t)row * ldC;
#pragma unroll
            for (int ni = 0; ni < 4; ni++) {
                int col = bn + wn * 32 + ni * 8 + (lane & 3) * 2;
                float v0 = acc[mi][ni][2 * h]     * alpha + rb + bc[2 * ni];
                float v1 = acc[mi][ni][2 * h + 1] * alpha + rb + bc[2 * ni + 1];
                if (res) {
                    v0 += res[(size_t)row * ldC + col];
                    v1 += res[(size_t)row * ldC + col + 1];
                }
                if (Cb) {
                    __nv_bfloat162 hv = __floats2bfloat162_rn(v0, v1);
                    *(__nv_bfloat162*)(Cb + rowbase + col) = hv;
                } else {
                    *(float2*)(Cf + rowbase + col) = make_float2(v0, v1);
                }
            }
        }
    }
}

// ---------------------------------------------------------------------------
// Row softmax: fp32 scores in, bf16 probabilities out. One block per row.
// ---------------------------------------------------------------------------
__global__ __launch_bounds__(256) void softmax_kernel(const float* __restrict__ S,
                                                      bf16* __restrict__ P) {
    const float4* p = (const float4*)(S + (size_t)blockIdx.x * NTOK);
    bf16* po = P + (size_t)blockIdx.x * NTOK;
    int tid = threadIdx.x;
    float4 loc[4];
    float m = -3.4e38f;
#pragma unroll
    for (int i = 0; i < 4; i++) {
        float4 v = p[tid + i * 256];
        loc[i] = v;
        m = fmaxf(m, fmaxf(fmaxf(v.x, v.y), fmaxf(v.z, v.w)));
    }
    __shared__ float red[256];
    red[tid] = m; __syncthreads();
    for (int st = 128; st > 0; st >>= 1) {
        if (tid < st) red[tid] = fmaxf(red[tid], red[tid + st]);
        __syncthreads();
    }
    m = red[0];
    __syncthreads();
    float ssum = 0.f;
#pragma unroll
    for (int i = 0; i < 4; i++) {
        loc[i].x = __expf(loc[i].x - m);
        loc[i].y = __expf(loc[i].y - m);
        loc[i].z = __expf(loc[i].z - m);
        loc[i].w = __expf(loc[i].w - m);
        ssum += loc[i].x + loc[i].y + loc[i].z + loc[i].w;
    }
    red[tid] = ssum; __syncthreads();
    for (int st = 128; st > 0; st >>= 1) {
        if (tid < st) red[tid] += red[tid + st];
        __syncthreads();
    }
    float inv = 1.f / red[0];
#pragma unroll
    for (int i = 0; i < 4; i++) {
        int el = (tid + i * 256) * 4;
        __nv_bfloat162 a = __floats2bfloat162_rn(loc[i].x * inv, loc[i].y * inv);
        __nv_bfloat162 b = __floats2bfloat162_rn(loc[i].z * inv, loc[i].w * inv);
        *(__nv_bfloat162*)(po + el)     = a;
        *(__nv_bfloat162*)(po + el + 2) = b;
    }
}

// ---------------------------------------------------------------------------
// Orchestration
// ---------------------------------------------------------------------------
extern "C" void kernel_launch(void* const* d_in, const int* in_sizes, int n_in,
                              void* d_out, int out_size) {
    const float* x  = (const float*)d_in[0];
    const float* gs = (const float*)d_in[1];
    const float* gb = (const float*)d_in[2];
    const float* wq = (const float*)d_in[3];
    const float* bq = (const float*)d_in[4];
    const float* wk = (const float*)d_in[5];
    const float* bk = (const float*)d_in[6];
    const float* wv = (const float*)d_in[7];
    const float* bv = (const float*)d_in[8];
    const float* wp = (const float*)d_in[9];
    const float* bp = (const float*)d_in[10];
    float* y = (float*)d_out;

    float* scratch = nullptr;
    cudaGetSymbolAddress((void**)&scratch, g_scratch);
    char* cb = (char*)scratch;

    const size_t NB1  = (size_t)NTOK * NCH;    // 2097152 elems / batch
    const size_t SB1  = (size_t)NTOK * NTOK;   // 16777216 elems / batch
    const size_t TB   = 2 * NB1 * 2;           // 8 MB  (bf16, 2 batches)
    const size_t WB   = (size_t)NCH * NCH * 2; // 512 KB per bf16 weight

    bf16* T  = (bf16*)cb;
    bf16* Wq = (bf16*)(cb + TB);
    bf16* Wk = (bf16*)(cb + TB + WB);
    bf16* Wv = (bf16*)(cb + TB + 2 * WB);
    bf16* Wp = (bf16*)(cb + TB + 3 * WB);
    bf16* Q  = (bf16*)(cb + TB + 4 * WB);
    bf16* Kb = (bf16*)(cb + TB + 4 * WB + TB);
    bf16* V  = (bf16*)(cb + TB + 4 * WB + 2 * TB);
    bf16* O  = (bf16*)(cb + TB + 4 * WB + 3 * TB);
    bf16* P  = (bf16*)(cb + TB + 4 * WB + 4 * TB);                 // 64 MB
    float* S = (float*)(cb + TB + 4 * WB + 4 * TB + 2 * SB1 * 2);  // 128 MB

    gn_kernel<<<64, 256>>>(x, gs, gb, T);
    cvt_kernel<<<256, 256>>>(wq, Wq);
    cvt_kernel<<<256, 256>>>(wk, Wk);
    cvt_kernel<<<256, 256>>>(wv, Wv);
    cvt_kernel<<<256, 256>>>(wp, Wp);

    // Q[b,n,c] = T . Wq^T + bq (col bias) -> bf16
    gemm_mma<<<dim3(4, 32, 2), 256>>>(
        T, Wq, NCH, NCH, NB1, 0, NB1, 1.f, nullptr, bq, nullptr, 0, nullptr, Q);
    // K[b,n,c] = T . Wk^T + bk (col bias) -> bf16
    gemm_mma<<<dim3(4, 32, 2), 256>>>(
        T, Wk, NCH, NCH, NB1, 0, NB1, 1.f, nullptr, bk, nullptr, 0, nullptr, Kb);
    // V[b,c,n] = Wv . T^T + bv (row bias) -> bf16
    gemm_mma<<<dim3(32, 4, 2), 256>>>(
        Wv, T, NCH, NTOK, 0, NB1, NB1, 1.f, bv, nullptr, nullptr, 0, nullptr, V);
    // S[b,n,n] = (Q . K^T) * c^-0.5 -> fp32
    gemm_mma<<<dim3(32, 32, 2), 256>>>(
        Q, Kb, NCH, NTOK, NB1, NB1, SB1, 0.044194173824159216f,
        nullptr, nullptr, nullptr, 0, S, nullptr);
    // softmax rows -> bf16 P
    softmax_kernel<<<2 * NTOK, 256>>>(S, P);
    // O[b,n,c] = P . V^T -> bf16
    gemm_mma<<<dim3(4, 32, 2), 256>>>(
        P, V, NTOK, NCH, SB1, NB1, NB1, 1.f, nullptr, nullptr, nullptr, 0,
        nullptr, O);
    // Y[b,c,n] = Wp . O^T + bp + x (row bias + residual) -> fp32
    gemm_mma<<<dim3(32, 4, 2), 256>>>(
        Wp, O, NCH, NTOK, 0, NB1, NB1, 1.f, bp, nullptr, x, NB1, y, nullptr);
}

// round 6
// speedup vs baseline: 5.4894x; 1.0541x over previous
#include <cuda_runtime.h>
#include <cuda_bf16.h>
#include <cstdint>
#include <cstddef>

#define NTOK 4096
#define NCH  512

typedef __nv_bfloat16 bf16;

// 256 MB static scratch (bss) — no runtime allocation.
__device__ float g_scratch[64u * 1024u * 1024u];

// ---------------------------------------------------------------------------
// PTX helpers (base sm_100 ISA only: cp.async, ldmatrix, mma.sync)
// ---------------------------------------------------------------------------
__device__ __forceinline__ uint32_t s2u(const void* p) {
    uint32_t r;
    asm("{ .reg .u64 t; cvta.to.shared.u64 t, %1; cvt.u32.u64 %0, t; }"
        : "=r"(r) : "l"(p));
    return r;
}
#define CP_ASYNC16(s, g)                                                       \
    asm volatile("cp.async.cg.shared.global [%0], [%1], 16;" ::                \
                 "r"(s), "l"(g))
#define CP_COMMIT() asm volatile("cp.async.commit_group;" ::: "memory")
#define CP_WAIT(n)  asm volatile("cp.async.wait_group %0;" :: "n"(n) : "memory")

__device__ __forceinline__ void ldm_x4(uint32_t& r0, uint32_t& r1,
                                       uint32_t& r2, uint32_t& r3,
                                       uint32_t addr) {
    asm volatile("ldmatrix.sync.aligned.m8n8.x4.shared.b16 {%0,%1,%2,%3}, [%4];"
                 : "=r"(r0), "=r"(r1), "=r"(r2), "=r"(r3) : "r"(addr));
}
__device__ __forceinline__ void mma16816(float* c, const uint32_t* a,
                                         uint32_t b0, uint32_t b1) {
    asm volatile(
        "mma.sync.aligned.m16n8k16.row.col.f32.bf16.bf16.f32 "
        "{%0,%1,%2,%3}, {%4,%5,%6,%7}, {%8,%9}, {%0,%1,%2,%3};"
        : "+f"(c[0]), "+f"(c[1]), "+f"(c[2]), "+f"(c[3])
        : "r"(a[0]), "r"(a[1]), "r"(a[2]), "r"(a[3]), "r"(b0), "r"(b1));
}

// ---------------------------------------------------------------------------
// GroupNorm: one block per (batch, group); writes transposed bf16 T[b][n][c].
// ---------------------------------------------------------------------------
__global__ __launch_bounds__(256) void gn_kernel(const float* __restrict__ x,
                                                 const float* __restrict__ sc,
                                                 const float* __restrict__ bi,
                                                 bf16* __restrict__ t) {
    int b = blockIdx.x >> 5;
    int g = blockIdx.x & 31;
    const float* base = x + ((size_t)(b * NCH + g * 16)) * NTOK;
    int tid = threadIdx.x;

    float s = 0.f, ss = 0.f;
    const float4* b4 = (const float4*)base;
    for (int i = tid; i < 16 * NTOK / 4; i += 256) {
        float4 v = b4[i];
        s  += v.x + v.y + v.z + v.w;
        ss += v.x * v.x + v.y * v.y + v.z * v.z + v.w * v.w;
    }
    __shared__ float rs[256], rss[256];
    rs[tid] = s; rss[tid] = ss;
    __syncthreads();
    for (int st = 128; st > 0; st >>= 1) {
        if (tid < st) { rs[tid] += rs[tid + st]; rss[tid] += rss[tid + st]; }
        __syncthreads();
    }
    float mean = rs[0] * (1.f / 65536.f);
    float var  = rss[0] * (1.f / 65536.f) - mean * mean;
    float inv  = rsqrtf(var + 1e-6f);

    __shared__ float Acf[16], Bcf[16];
    if (tid < 16) {
        float scv = sc[g * 16 + tid], biv = bi[g * 16 + tid];
        Acf[tid] = scv * inv;
        Bcf[tid] = biv - mean * scv * inv;
    }
    __shared__ float tile[16][257];
    __syncthreads();

    for (int tb = 0; tb < 16; tb++) {
        int p0 = tb * 256;
        for (int idx = tid; idx < 4096; idx += 256) {
            int cc = idx >> 8, pp = idx & 255;
            tile[cc][pp] = base[cc * NTOK + p0 + pp] * Acf[cc] + Bcf[cc];
        }
        __syncthreads();
        for (int idx = tid; idx < 4096; idx += 256) {
            int pp = idx >> 4, cc = idx & 15;
            t[((size_t)(b * NTOK + p0 + pp)) * NCH + g * 16 + cc] =
                __float2bfloat16(tile[cc][pp]);
        }
        __syncthreads();
    }
}

// ---------------------------------------------------------------------------
// fp32 -> bf16 conversion for all 4 weight matrices in one launch.
// grid = 1024 blocks; blocks [256*w, 256*w+255] handle weight w.
// ---------------------------------------------------------------------------
__global__ __launch_bounds__(256) void cvt4_kernel(
    const float* __restrict__ w0, const float* __restrict__ w1,
    const float* __restrict__ w2, const float* __restrict__ w3,
    bf16* __restrict__ o0, bf16* __restrict__ o1,
    bf16* __restrict__ o2, bf16* __restrict__ o3) {
    int which = blockIdx.x >> 8;
    const float* in = (which == 0) ? w0 : (which == 1) ? w1 :
                      (which == 2) ? w2 : w3;
    bf16* out = (which == 0) ? o0 : (which == 1) ? o1 :
                (which == 2) ? o2 : o3;
    int i = (blockIdx.x & 255) * 256 + threadIdx.x;
    float4 v = ((const float4*)in)[i];
    __nv_bfloat162 a = __floats2bfloat162_rn(v.x, v.y);
    __nv_bfloat162 b = __floats2bfloat162_rn(v.z, v.w);
    ((__nv_bfloat162*)out)[2 * i]     = a;
    ((__nv_bfloat162*)out)[2 * i + 1] = b;
}

// ---------------------------------------------------------------------------
// bf16 mma.sync GEMM: C[M,N] = alpha * A[M,K] . B[N,K]^T (+biases/residual).
// CTA tile 128x128, BK=32, 8 warps (2 M x 4 N), warp tile 64x32.
// 3-stage cp.async pipeline, ONE __syncthreads per K-iteration.
// Smem rows padded to 80B (stride 5 x 16B, coprime 8) -> conflict-free ldmatrix.
// grid = (N/128, M/128, batch). All dims are multiples of tile sizes.
// ---------------------------------------------------------------------------
#define STG_BYTES 20480   // A: 128*80, B: 128*80
#define GEMM_SMEM (3 * STG_BYTES)
__global__ __launch_bounds__(256, 2) void gemm_mma(
    const bf16* __restrict__ A, const bf16* __restrict__ B,
    int K, int ldC,
    size_t sA, size_t sB, size_t sC,
    float alpha,
    const float* __restrict__ brow, const float* __restrict__ bcol,
    const float* __restrict__ res, size_t sRes,
    float* __restrict__ Cf, bf16* __restrict__ Cb) {
    extern __shared__ __align__(16) char smem[];

    const int tid = threadIdx.x;
    const int wid = tid >> 5, lane = tid & 31;
    const int wm = wid & 1, wn = wid >> 1;       // 2 x 4 warp grid
    const int bm = blockIdx.y * 128, bn = blockIdx.x * 128;
    A += (size_t)blockIdx.z * sA;
    B += (size_t)blockIdx.z * sB;
    const size_t coff = (size_t)blockIdx.z * sC;
    if (res) res += (size_t)blockIdx.z * sRes;

    const bf16* Ab = A + (size_t)bm * K;
    const bf16* Bb = B + (size_t)bn * K;
    const int NC = K >> 5;                       // >= 16 for all our shapes

    // loader: 2x (A chunk + B chunk) 16B per thread per stage
    const int lr0 = tid >> 2;            // rows 0..63 (+64 for j=1)
    const int lcb = (tid & 3) * 16;      // byte col within 64B k-row

    float acc[4][4][4];
#pragma unroll
    for (int mi = 0; mi < 4; mi++)
#pragma unroll
        for (int ni = 0; ni < 4; ni++)
#pragma unroll
            for (int q = 0; q < 4; q++) acc[mi][ni][q] = 0.f;

    // ldmatrix base offsets (bytes within a stage): row stride 80
    uint32_t aoff[4], boff[2];
#pragma unroll
    for (int mi = 0; mi < 4; mi++)
        aoff[mi] = (uint32_t)((wm * 64 + mi * 16 + (lane & 15)) * 80 +
                              (lane >> 4) * 16);
#pragma unroll
    for (int nb = 0; nb < 2; nb++)
        boff[nb] = (uint32_t)(10240 + (wn * 32 + nb * 16 + (lane & 15)) * 80 +
                              (lane >> 4) * 16);

    const uint32_t sbase = s2u(smem);

    // stage issue helper (manual): loads k-slab `ks32` into stage buffer `st`
#define ISSUE(st, ks32)                                                        \
    do {                                                                       \
        uint32_t sa = sbase + (st) * STG_BYTES;                                \
        const bf16* Ag = Ab + (ks32) * 32;                                     \
        const bf16* Bg = Bb + (ks32) * 32;                                     \
        _Pragma("unroll")                                                      \
        for (int j = 0; j < 2; j++) {                                          \
            int r = lr0 + j * 64;                                              \
            CP_ASYNC16(sa + r * 80 + lcb,                                      \
                       (const char*)(Ag + (size_t)r * K) + lcb);               \
            CP_ASYNC16(sa + 10240 + r * 80 + lcb,                              \
                       (const char*)(Bg + (size_t)r * K) + lcb);               \
        }                                                                      \
    } while (0)

    // prologue: stages 0 and 1 (two groups)
    ISSUE(0, 0); CP_COMMIT();
    ISSUE(1, 1); CP_COMMIT();

    int st = 0;                                   // stage of iter i
    for (int i = 0; i < NC; i++) {
        // group i must be complete before compute; latest committed group is
        // min(i+1, NC-1) -> allowed pending = 1 except on the last iter.
        if (i + 1 < NC) { CP_WAIT(1); } else { CP_WAIT(0); }
        __syncthreads();   // also: all warps done reading stage (i+2)%3 @ i-1
        if (i + 2 < NC) {
            int wstage = st + 2; if (wstage >= 3) wstage -= 3;
            ISSUE(wstage, i + 2); CP_COMMIT();
        }

        uint32_t base = sbase + st * STG_BYTES;
#pragma unroll
        for (int ks = 0; ks < 2; ks++) {
            uint32_t areg[4][4], breg[2][4];
#pragma unroll
            for (int mi = 0; mi < 4; mi++)
                ldm_x4(areg[mi][0], areg[mi][1], areg[mi][2], areg[mi][3],
                       base + aoff[mi] + ks * 32);
#pragma unroll
            for (int nb = 0; nb < 2; nb++)
                ldm_x4(breg[nb][0], breg[nb][1], breg[nb][2], breg[nb][3],
                       base + boff[nb] + ks * 32);
#pragma unroll
            for (int mi = 0; mi < 4; mi++)
#pragma unroll
                for (int ni = 0; ni < 4; ni++) {
                    uint32_t b0 = breg[ni >> 1][ni & 1];
                    uint32_t b1 = breg[ni >> 1][(ni & 1) + 2];
                    mma16816(acc[mi][ni], areg[mi], b0, b1);
                }
        }
        st++; if (st >= 3) st = 0;
    }
#undef ISSUE

    // ---- epilogue ----
    float bc[8];
#pragma unroll
    for (int ni = 0; ni < 4; ni++) {
        int col = bn + wn * 32 + ni * 8 + (lane & 3) * 2;
        bc[2 * ni]     = bcol ? bcol[col]     : 0.f;
        bc[2 * ni + 1] = bcol ? bcol[col + 1] : 0.f;
    }
#pragma unroll
    for (int mi = 0; mi < 4; mi++) {
#pragma unroll
        for (int h = 0; h < 2; h++) {
            int row = bm + wm * 64 + mi * 16 + (lane >> 2) + 8 * h;
            float rb = brow ? brow[row] : 0.f;
            size_t rowbase = coff + (size_t)row * ldC;
#pragma unroll
            for (int ni = 0; ni < 4; ni++) {
                int col = bn + wn * 32 + ni * 8 + (lane & 3) * 2;
                float v0 = acc[mi][ni][2 * h]     * alpha + rb + bc[2 * ni];
                float v1 = acc[mi][ni][2 * h + 1] * alpha + rb + bc[2 * ni + 1];
                if (res) {
                    v0 += res[(size_t)row * ldC + col];
                    v1 += res[(size_t)row * ldC + col + 1];
                }
                if (Cb) {
                    __nv_bfloat162 hv = __floats2bfloat162_rn(v0, v1);
                    *(__nv_bfloat162*)(Cb + rowbase + col) = hv;
                } else {
                    *(float2*)(Cf + rowbase + col) = make_float2(v0, v1);
                }
            }
        }
    }
}

// ---------------------------------------------------------------------------
// Row softmax: bf16 scores in, bf16 probabilities out. One block per row.
// ---------------------------------------------------------------------------
__global__ __launch_bounds__(256) void softmax_kernel(const bf16* __restrict__ S,
                                                      bf16* __restrict__ P) {
    const uint4* p = (const uint4*)(S + (size_t)blockIdx.x * NTOK);  // 8 bf16
    bf16* po = P + (size_t)blockIdx.x * NTOK;
    int tid = threadIdx.x;
    float loc[16];
    float m = -3.4e38f;
#pragma unroll
    for (int i = 0; i < 2; i++) {
        uint4 v = p[tid + i * 256];
        const uint32_t w[4] = { v.x, v.y, v.z, v.w };
#pragma unroll
        for (int q = 0; q < 4; q++) {
            float2 f = __bfloat1622float2(*(const __nv_bfloat162*)&w[q]);
            loc[i * 8 + 2 * q]     = f.x;
            loc[i * 8 + 2 * q + 1] = f.y;
            m = fmaxf(m, fmaxf(f.x, f.y));
        }
    }
    __shared__ float red[256];
    red[tid] = m; __syncthreads();
    for (int st = 128; st > 0; st >>= 1) {
        if (tid < st) red[tid] = fmaxf(red[tid], red[tid + st]);
        __syncthreads();
    }
    m = red[0];
    __syncthreads();
    float ssum = 0.f;
#pragma unroll
    for (int i = 0; i < 16; i++) {
        loc[i] = __expf(loc[i] - m);
        ssum += loc[i];
    }
    red[tid] = ssum; __syncthreads();
    for (int st = 128; st > 0; st >>= 1) {
        if (tid < st) red[tid] += red[tid + st];
        __syncthreads();
    }
    float inv = 1.f / red[0];
#pragma unroll
    for (int i = 0; i < 2; i++) {
        uint32_t w[4];
#pragma unroll
        for (int q = 0; q < 4; q++) {
            __nv_bfloat162 h = __floats2bfloat162_rn(
                loc[i * 8 + 2 * q] * inv, loc[i * 8 + 2 * q + 1] * inv);
            w[q] = *(uint32_t*)&h;
        }
        ((uint4*)po)[tid + i * 256] = make_uint4(w[0], w[1], w[2], w[3]);
    }
}

// ---------------------------------------------------------------------------
// Orchestration
// ---------------------------------------------------------------------------
extern "C" void kernel_launch(void* const* d_in, const int* in_sizes, int n_in,
                              void* d_out, int out_size) {
    const float* x  = (const float*)d_in[0];
    const float* gs = (const float*)d_in[1];
    const float* gb = (const float*)d_in[2];
    const float* wq = (const float*)d_in[3];
    const float* bq = (const float*)d_in[4];
    const float* wk = (const float*)d_in[5];
    const float* bk = (const float*)d_in[6];
    const float* wv = (const float*)d_in[7];
    const float* bv = (const float*)d_in[8];
    const float* wp = (const float*)d_in[9];
    const float* bp = (const float*)d_in[10];
    float* y = (float*)d_out;

    float* scratch = nullptr;
    cudaGetSymbolAddress((void**)&scratch, g_scratch);
    char* cb = (char*)scratch;

    const size_t NB1  = (size_t)NTOK * NCH;    // 2097152 elems / batch
    const size_t SB1  = (size_t)NTOK * NTOK;   // 16777216 elems / batch
    const size_t TB   = 2 * NB1 * 2;           // 8 MB  (bf16, 2 batches)
    const size_t WB   = (size_t)NCH * NCH * 2; // 512 KB per bf16 weight

    bf16* T  = (bf16*)cb;
    bf16* Wq = (bf16*)(cb + TB);
    bf16* Wk = (bf16*)(cb + TB + WB);
    bf16* Wv = (bf16*)(cb + TB + 2 * WB);
    bf16* Wp = (bf16*)(cb + TB + 3 * WB);
    bf16* Q  = (bf16*)(cb + TB + 4 * WB);
    bf16* Kb = (bf16*)(cb + TB + 4 * WB + TB);
    bf16* V  = (bf16*)(cb + TB + 4 * WB + 2 * TB);
    bf16* O  = (bf16*)(cb + TB + 4 * WB + 3 * TB);
    bf16* P  = (bf16*)(cb + TB + 4 * WB + 4 * TB);                 // 64 MB
    bf16* S  = (bf16*)(cb + TB + 4 * WB + 4 * TB + 2 * SB1 * 2);   // 64 MB

    cudaFuncSetAttribute(gemm_mma, cudaFuncAttributeMaxDynamicSharedMemorySize,
                         GEMM_SMEM);

    gn_kernel<<<64, 256>>>(x, gs, gb, T);
    cvt4_kernel<<<1024, 256>>>(wq, wk, wv, wp, Wq, Wk, Wv, Wp);

    // Q[b,n,c] = T . Wq^T + bq (col bias) -> bf16
    gemm_mma<<<dim3(4, 32, 2), 256, GEMM_SMEM>>>(
        T, Wq, NCH, NCH, NB1, 0, NB1, 1.f, nullptr, bq, nullptr, 0, nullptr, Q);
    // K[b,n,c] = T . Wk^T + bk (col bias) -> bf16
    gemm_mma<<<dim3(4, 32, 2), 256, GEMM_SMEM>>>(
        T, Wk, NCH, NCH, NB1, 0, NB1, 1.f, nullptr, bk, nullptr, 0, nullptr, Kb);
    // V[b,c,n] = Wv . T^T + bv (row bias) -> bf16
    gemm_mma<<<dim3(32, 4, 2), 256, GEMM_SMEM>>>(
        Wv, T, NCH, NTOK, 0, NB1, NB1, 1.f, bv, nullptr, nullptr, 0, nullptr, V);
    // S[b,n,n] = (Q . K^T) * c^-0.5 -> bf16
    gemm_mma<<<dim3(32, 32, 2), 256, GEMM_SMEM>>>(
        Q, Kb, NCH, NTOK, NB1, NB1, SB1, 0.044194173824159216f,
        nullptr, nullptr, nullptr, 0, nullptr, S);
    // softmax rows -> bf16 P
    softmax_kernel<<<2 * NTOK, 256>>>(S, P);
    // O[b,n,c] = P . V^T -> bf16
    gemm_mma<<<dim3(4, 32, 2), 256, GEMM_SMEM>>>(
        P, V, NTOK, NCH, SB1, NB1, NB1, 1.f, nullptr, nullptr, nullptr, 0,
        nullptr, O);
    // Y[b,c,n] = Wp . O^T + bp + x (row bias + residual) -> fp32
    gemm_mma<<<dim3(32, 4, 2), 256, GEMM_SMEM>>>(
        Wp, O, NCH, NTOK, 0, NB1, NB1, 1.f, bp, nullptr, x, NB1, y, nullptr);
}

// round 7
// speedup vs baseline: 6.3796x; 1.1622x over previous
#include <cuda_runtime.h>
#include <cuda_bf16.h>
#include <cstdint>
#include <cstddef>

#define NTOK 4096
#define NCH  512

typedef __nv_bfloat16 bf16;

// 256 MB static scratch (bss) — no runtime allocation.
__device__ float g_scratch[64u * 1024u * 1024u];

// ---------------------------------------------------------------------------
// PTX helpers (base sm_100 ISA only: cp.async, ldmatrix, mma.sync)
// ---------------------------------------------------------------------------
__device__ __forceinline__ uint32_t s2u(const void* p) {
    uint32_t r;
    asm("{ .reg .u64 t; cvta.to.shared.u64 t, %1; cvt.u32.u64 %0, t; }"
        : "=r"(r) : "l"(p));
    return r;
}
#define CP_ASYNC16(s, g)                                                       \
    asm volatile("cp.async.cg.shared.global [%0], [%1], 16;" ::                \
                 "r"(s), "l"(g))
#define CP_COMMIT() asm volatile("cp.async.commit_group;" ::: "memory")
#define CP_WAIT(n)  asm volatile("cp.async.wait_group %0;" :: "n"(n) : "memory")

__device__ __forceinline__ void ldm_x4(uint32_t& r0, uint32_t& r1,
                                       uint32_t& r2, uint32_t& r3,
                                       uint32_t addr) {
    asm volatile("ldmatrix.sync.aligned.m8n8.x4.shared.b16 {%0,%1,%2,%3}, [%4];"
                 : "=r"(r0), "=r"(r1), "=r"(r2), "=r"(r3) : "r"(addr));
}
__device__ __forceinline__ void mma16816(float* c, const uint32_t* a,
                                         uint32_t b0, uint32_t b1) {
    asm volatile(
        "mma.sync.aligned.m16n8k16.row.col.f32.bf16.bf16.f32 "
        "{%0,%1,%2,%3}, {%4,%5,%6,%7}, {%8,%9}, {%0,%1,%2,%3};"
        : "+f"(c[0]), "+f"(c[1]), "+f"(c[2]), "+f"(c[3])
        : "r"(a[0]), "r"(a[1]), "r"(a[2]), "r"(a[3]), "r"(b0), "r"(b1));
}

// ---------------------------------------------------------------------------
// GroupNorm: one block per (batch, group); writes transposed bf16 T[b][n][c].
// ---------------------------------------------------------------------------
__global__ __launch_bounds__(256) void gn_kernel(const float* __restrict__ x,
                                                 const float* __restrict__ sc,
                                                 const float* __restrict__ bi,
                                                 bf16* __restrict__ t) {
    int b = blockIdx.x >> 5;
    int g = blockIdx.x & 31;
    const float* base = x + ((size_t)(b * NCH + g * 16)) * NTOK;
    int tid = threadIdx.x;

    float s = 0.f, ss = 0.f;
    const float4* b4 = (const float4*)base;
    for (int i = tid; i < 16 * NTOK / 4; i += 256) {
        float4 v = b4[i];
        s  += v.x + v.y + v.z + v.w;
        ss += v.x * v.x + v.y * v.y + v.z * v.z + v.w * v.w;
    }
    __shared__ float rs[256], rss[256];
    rs[tid] = s; rss[tid] = ss;
    __syncthreads();
    for (int st = 128; st > 0; st >>= 1) {
        if (tid < st) { rs[tid] += rs[tid + st]; rss[tid] += rss[tid + st]; }
        __syncthreads();
    }
    float mean = rs[0] * (1.f / 65536.f);
    float var  = rss[0] * (1.f / 65536.f) - mean * mean;
    float inv  = rsqrtf(var + 1e-6f);

    __shared__ float Acf[16], Bcf[16];
    if (tid < 16) {
        float scv = sc[g * 16 + tid], biv = bi[g * 16 + tid];
        Acf[tid] = scv * inv;
        Bcf[tid] = biv - mean * scv * inv;
    }
    __shared__ float tile[16][257];
    __syncthreads();

    for (int tb = 0; tb < 16; tb++) {
        int p0 = tb * 256;
        for (int idx = tid; idx < 4096; idx += 256) {
            int cc = idx >> 8, pp = idx & 255;
            tile[cc][pp] = base[cc * NTOK + p0 + pp] * Acf[cc] + Bcf[cc];
        }
        __syncthreads();
        for (int idx = tid; idx < 4096; idx += 256) {
            int pp = idx >> 4, cc = idx & 15;
            t[((size_t)(b * NTOK + p0 + pp)) * NCH + g * 16 + cc] =
                __float2bfloat16(tile[cc][pp]);
        }
        __syncthreads();
    }
}

// ---------------------------------------------------------------------------
// fp32 -> bf16 conversion: wq,wk go into one stacked Wqk [1024x512]; wv, wp
// separate. Also concatenates bq||bk into bqk (fp32) using the first block.
// ---------------------------------------------------------------------------
__global__ __launch_bounds__(256) void cvt4_kernel(
    const float* __restrict__ w0, const float* __restrict__ w1,
    const float* __restrict__ w2, const float* __restrict__ w3,
    bf16* __restrict__ o01, bf16* __restrict__ o2, bf16* __restrict__ o3,
    const float* __restrict__ bq, const float* __restrict__ bk,
    float* __restrict__ bqk) {
    if (blockIdx.x == 1024) {  // bias concat block
        int i = threadIdx.x;
        bqk[i]       = bq[i];
        bqk[i + 256] = bq[i + 256];
        bqk[i + 512] = bk[i];
        bqk[i + 768] = bk[i + 256];
        return;
    }
    int which = blockIdx.x >> 8;
    const float* in = (which == 0) ? w0 : (which == 1) ? w1 :
                      (which == 2) ? w2 : w3;
    bf16* out = (which == 0) ? o01 : (which == 1) ? (o01 + 512 * 512) :
                (which == 2) ? o2 : o3;
    int i = (blockIdx.x & 255) * 256 + threadIdx.x;
    float4 v = ((const float4*)in)[i];
    __nv_bfloat162 a = __floats2bfloat162_rn(v.x, v.y);
    __nv_bfloat162 b = __floats2bfloat162_rn(v.z, v.w);
    ((__nv_bfloat162*)out)[2 * i]     = a;
    ((__nv_bfloat162*)out)[2 * i + 1] = b;
}

// ---------------------------------------------------------------------------
// bf16 mma.sync GEMM: C[M,N] = alpha * A[M,K] . B[N,K]^T (+biases/residual).
// CTA tile 128x128, BK=64, 8 warps (2 M x 4 N), warp tile 64x32.
// 3-stage cp.async pipeline, ONE __syncthreads per 64-wide K-iteration.
// Smem: XOR-swizzled 128B rows (Swizzle<3,4,3>) -> no padding, conflict-free
// ldmatrix, 32KB/stage.  A,B have independent leading dims lda/ldb (elements).
// grid = (N/128, M/128, batch). All dims are multiples of tile sizes; K%64==0.
// ---------------------------------------------------------------------------
#define STG 32768            // A: 128*128B, B: 128*128B
#define GEMM_SMEM (3 * STG)
__global__ __launch_bounds__(256, 2) void gemm_mma(
    const bf16* __restrict__ A, const bf16* __restrict__ B,
    int K, int lda, int ldb, int ldC,
    size_t sA, size_t sB, size_t sC,
    float alpha,
    const float* __restrict__ brow, const float* __restrict__ bcol,
    const float* __restrict__ res, size_t sRes,
    float* __restrict__ Cf, bf16* __restrict__ Cb) {
    extern __shared__ __align__(16) char smem[];

    const int tid = threadIdx.x;
    const int wid = tid >> 5, lane = tid & 31;
    const int wm = wid & 1, wn = wid >> 1;       // 2 x 4 warp grid
    const int bm = blockIdx.y * 128, bn = blockIdx.x * 128;
    A += (size_t)blockIdx.z * sA;
    B += (size_t)blockIdx.z * sB;
    const size_t coff = (size_t)blockIdx.z * sC;
    if (res) res += (size_t)blockIdx.z * sRes;

    const int NC = K >> 6;                       // >= 8 for all our shapes

    // ---- loader setup: 8 x 16B cp.async per thread per stage ----
    const int lr  = tid >> 2;                    // rows lr, lr+64
    const int lcb = (tid & 3) * 16;              // byte cols lcb, lcb+64
    const uint32_t lsc  = (uint32_t)((lr & 7) << 4);     // swizzle const
    const uint32_t c0s  = (uint32_t)lcb ^ lsc;
    const uint32_t c1s  = c0s ^ 64u;
    const uint32_t ro0  = (uint32_t)(lr * 128);
    const uint32_t ro1  = ro0 + 64 * 128;
    const size_t lda2 = (size_t)lda * 2, ldb2 = (size_t)ldb * 2;
    const char* aR0 = (const char*)(A + (size_t)(bm + lr) * lda) + lcb;
    const char* aR1 = aR0 + 64 * lda2;
    const char* bR0 = (const char*)(B + (size_t)(bn + lr) * ldb) + lcb;
    const char* bR1 = bR0 + 64 * ldb2;

    float acc[4][4][4];
#pragma unroll
    for (int mi = 0; mi < 4; mi++)
#pragma unroll
        for (int ni = 0; ni < 4; ni++)
#pragma unroll
            for (int q = 0; q < 4; q++) acc[mi][ni][q] = 0.f;

    // ---- ldmatrix setup (per-lane) ----
    const uint32_t msc = (uint32_t)((lane & 7) << 4);    // row&7 == lane&7
    const uint32_t h16 = (uint32_t)((lane >> 4) << 4);
    uint32_t kc[4];
#pragma unroll
    for (int ks = 0; ks < 4; ks++) kc[ks] = ((uint32_t)(ks * 32) + h16) ^ msc;
    uint32_t arow[4], brow_off[2];
#pragma unroll
    for (int mi = 0; mi < 4; mi++)
        arow[mi] = (uint32_t)((wm * 64 + mi * 16 + (lane & 15)) * 128);
#pragma unroll
    for (int nb = 0; nb < 2; nb++)
        brow_off[nb] = (uint32_t)(16384 + (wn * 32 + nb * 16 + (lane & 15)) * 128);

    const uint32_t sbase = s2u(smem);

#define ISSUE(st_, i_)                                                         \
    do {                                                                       \
        uint32_t sa = sbase + (uint32_t)(st_) * STG;                           \
        size_t kb = (size_t)(i_) * 128;                                        \
        CP_ASYNC16(sa + ro0 + c0s,          aR0 + kb);                         \
        CP_ASYNC16(sa + ro0 + c1s,          aR0 + kb + 64);                    \
        CP_ASYNC16(sa + ro1 + c0s,          aR1 + kb);                         \
        CP_ASYNC16(sa + ro1 + c1s,          aR1 + kb + 64);                    \
        CP_ASYNC16(sa + 16384 + ro0 + c0s,  bR0 + kb);                         \
        CP_ASYNC16(sa + 16384 + ro0 + c1s,  bR0 + kb + 64);                    \
        CP_ASYNC16(sa + 16384 + ro1 + c0s,  bR1 + kb);                         \
        CP_ASYNC16(sa + 16384 + ro1 + c1s,  bR1 + kb + 64);                    \
    } while (0)

    ISSUE(0, 0); CP_COMMIT();
    ISSUE(1, 1); CP_COMMIT();

    int st = 0;
    for (int i = 0; i < NC; i++) {
        if (i + 1 < NC) { CP_WAIT(1); } else { CP_WAIT(0); }
        __syncthreads();
        if (i + 2 < NC) {
            int w2 = st + 2; if (w2 >= 3) w2 -= 3;
            ISSUE(w2, i + 2); CP_COMMIT();
        }

        uint32_t base = sbase + (uint32_t)st * STG;
#pragma unroll
        for (int ks = 0; ks < 4; ks++) {
            uint32_t areg[4][4], breg[2][4];
#pragma unroll
            for (int mi = 0; mi < 4; mi++)
                ldm_x4(areg[mi][0], areg[mi][1], areg[mi][2], areg[mi][3],
                       base + arow[mi] + kc[ks]);
#pragma unroll
            for (int nb = 0; nb < 2; nb++)
                ldm_x4(breg[nb][0], breg[nb][1], breg[nb][2], breg[nb][3],
                       base + brow_off[nb] + kc[ks]);
#pragma unroll
            for (int mi = 0; mi < 4; mi++)
#pragma unroll
                for (int ni = 0; ni < 4; ni++) {
                    uint32_t b0 = breg[ni >> 1][ni & 1];
                    uint32_t b1 = breg[ni >> 1][(ni & 1) + 2];
                    mma16816(acc[mi][ni], areg[mi], b0, b1);
                }
        }
        st++; if (st >= 3) st = 0;
    }
#undef ISSUE

    // ---- epilogue ----
    float bc[8];
#pragma unroll
    for (int ni = 0; ni < 4; ni++) {
        int col = bn + wn * 32 + ni * 8 + (lane & 3) * 2;
        bc[2 * ni]     = bcol ? bcol[col]     : 0.f;
        bc[2 * ni + 1] = bcol ? bcol[col + 1] : 0.f;
    }
#pragma unroll
    for (int mi = 0; mi < 4; mi++) {
#pragma unroll
        for (int h = 0; h < 2; h++) {
            int row = bm + wm * 64 + mi * 16 + (lane >> 2) + 8 * h;
            float rb = brow ? brow[row] : 0.f;
            size_t rowbase = coff + (size_t)row * ldC;
#pragma unroll
            for (int ni = 0; ni < 4; ni++) {
                int col = bn + wn * 32 + ni * 8 + (lane & 3) * 2;
                float v0 = acc[mi][ni][2 * h]     * alpha + rb + bc[2 * ni];
                float v1 = acc[mi][ni][2 * h + 1] * alpha + rb + bc[2 * ni + 1];
                if (res) {
                    v0 += res[(size_t)row * ldC + col];
                    v1 += res[(size_t)row * ldC + col + 1];
                }
                if (Cb) {
                    __nv_bfloat162 hv = __floats2bfloat162_rn(v0, v1);
                    *(__nv_bfloat162*)(Cb + rowbase + col) = hv;
                } else {
                    *(float2*)(Cf + rowbase + col) = make_float2(v0, v1);
                }
            }
        }
    }
}

// ---------------------------------------------------------------------------
// Row softmax: bf16 scores in, bf16 probabilities out. One block per row.
// ---------------------------------------------------------------------------
__global__ __launch_bounds__(256) void softmax_kernel(const bf16* __restrict__ S,
                                                      bf16* __restrict__ P) {
    const uint4* p = (const uint4*)(S + (size_t)blockIdx.x * NTOK);  // 8 bf16
    bf16* po = P + (size_t)blockIdx.x * NTOK;
    int tid = threadIdx.x;
    float loc[16];
    float m = -3.4e38f;
#pragma unroll
    for (int i = 0; i < 2; i++) {
        uint4 v = p[tid + i * 256];
        const uint32_t w[4] = { v.x, v.y, v.z, v.w };
#pragma unroll
        for (int q = 0; q < 4; q++) {
            float2 f = __bfloat1622float2(*(const __nv_bfloat162*)&w[q]);
            loc[i * 8 + 2 * q]     = f.x;
            loc[i * 8 + 2 * q + 1] = f.y;
            m = fmaxf(m, fmaxf(f.x, f.y));
        }
    }
    __shared__ float red[256];
    red[tid] = m; __syncthreads();
    for (int st = 128; st > 0; st >>= 1) {
        if (tid < st) red[tid] = fmaxf(red[tid], red[tid + st]);
        __syncthreads();
    }
    m = red[0];
    __syncthreads();
    float ssum = 0.f;
#pragma unroll
    for (int i = 0; i < 16; i++) {
        loc[i] = __expf(loc[i] - m);
        ssum += loc[i];
    }
    red[tid] = ssum; __syncthreads();
    for (int st = 128; st > 0; st >>= 1) {
        if (tid < st) red[tid] += red[tid + st];
        __syncthreads();
    }
    float inv = 1.f / red[0];
#pragma unroll
    for (int i = 0; i < 2; i++) {
        uint32_t w[4];
#pragma unroll
        for (int q = 0; q < 4; q++) {
            __nv_bfloat162 h = __floats2bfloat162_rn(
                loc[i * 8 + 2 * q] * inv, loc[i * 8 + 2 * q + 1] * inv);
            w[q] = *(uint32_t*)&h;
        }
        ((uint4*)po)[tid + i * 256] = make_uint4(w[0], w[1], w[2], w[3]);
    }
}

// ---------------------------------------------------------------------------
// Orchestration
// ---------------------------------------------------------------------------
extern "C" void kernel_launch(void* const* d_in, const int* in_sizes, int n_in,
                              void* d_out, int out_size) {
    const float* x  = (const float*)d_in[0];
    const float* gs = (const float*)d_in[1];
    const float* gb = (const float*)d_in[2];
    const float* wq = (const float*)d_in[3];
    const float* bq = (const float*)d_in[4];
    const float* wk = (const float*)d_in[5];
    const float* bk = (const float*)d_in[6];
    const float* wv = (const float*)d_in[7];
    const float* bv = (const float*)d_in[8];
    const float* wp = (const float*)d_in[9];
    const float* bp = (const float*)d_in[10];
    float* y = (float*)d_out;

    float* scratch = nullptr;
    cudaGetSymbolAddress((void**)&scratch, g_scratch);
    char* cb = (char*)scratch;

    const size_t NB1  = (size_t)NTOK * NCH;    // 2097152 elems / batch
    const size_t SB1  = (size_t)NTOK * NTOK;   // 16777216 elems / batch
    const size_t TB   = 2 * NB1 * 2;           // 8 MB  (bf16, 2 batches)
    const size_t WB   = (size_t)NCH * NCH * 2; // 512 KB per bf16 weight

    bf16*  T   = (bf16*)cb;                                 // 8 MB
    bf16*  Wqk = (bf16*)(cb + TB);                          // 1 MB (stacked)
    bf16*  Wv  = (bf16*)(cb + TB + 2 * WB);
    bf16*  Wp  = (bf16*)(cb + TB + 3 * WB);
    float* bqk = (float*)(cb + TB + 4 * WB);                // 4 KB
    bf16*  QK  = (bf16*)(cb + TB + 4 * WB + 8192);          // 16 MB
    bf16*  V   = (bf16*)((char*)QK + 4 * NB1 * 2);          // 8 MB
    bf16*  O   = (bf16*)((char*)V + TB);                    // 8 MB
    bf16*  P   = (bf16*)((char*)O + TB);                    // 64 MB
    bf16*  S   = (bf16*)((char*)P + 2 * SB1 * 2);           // 64 MB

    cudaFuncSetAttribute(gemm_mma, cudaFuncAttributeMaxDynamicSharedMemorySize,
                         GEMM_SMEM);

    gn_kernel<<<64, 256>>>(x, gs, gb, T);
    cvt4_kernel<<<1025, 256>>>(wq, wk, wv, wp, Wqk, Wv, Wp, bq, bk, bqk);

    // QK[b,n,0:1024] = T . Wqk^T + bqk (col bias) -> bf16  (Q cols 0-511, K 512-1023)
    gemm_mma<<<dim3(8, 32, 2), 256, GEMM_SMEM>>>(
        T, Wqk, NCH, NCH, NCH, 1024, NB1, 0, 2 * NB1, 1.f,
        nullptr, bqk, nullptr, 0, nullptr, QK);
    // V[b,c,n] = Wv . T^T + bv (row bias) -> bf16
    gemm_mma<<<dim3(32, 4, 2), 256, GEMM_SMEM>>>(
        Wv, T, NCH, NCH, NCH, NTOK, 0, NB1, NB1, 1.f,
        bv, nullptr, nullptr, 0, nullptr, V);
    // S[b,n,n] = (Q . K^T) * c^-0.5 -> bf16   (Q, K are strided slices of QK)
    gemm_mma<<<dim3(32, 32, 2), 256, GEMM_SMEM>>>(
        QK, QK + 512, NCH, 1024, 1024, NTOK, 2 * NB1, 2 * NB1, SB1,
        0.044194173824159216f, nullptr, nullptr, nullptr, 0, nullptr, S);
    // softmax rows -> bf16 P
    softmax_kernel<<<2 * NTOK, 256>>>(S, P);
    // O[b,n,c] = P . V^T -> bf16
    gemm_mma<<<dim3(4, 32, 2), 256, GEMM_SMEM>>>(
        P, V, NTOK, NTOK, NTOK, NCH, SB1, NB1, NB1, 1.f,
        nullptr, nullptr, nullptr, 0, nullptr, O);
    // Y[b,c,n] = Wp . O^T + bp + x (row bias + residual) -> fp32
    gemm_mma<<<dim3(32, 4, 2), 256, GEMM_SMEM>>>(
        Wp, O, NCH, NCH, NCH, NTOK, 0, NB1, NB1, 1.f,
        bp, nullptr, x, NB1, y, nullptr);
}